// round 5
// baseline (speedup 1.0000x reference)
#include <cuda_runtime.h>
#include <cstdint>

// SpikeFP32Embedding: out[t, :] = weight_pulse[token_ids[t], :]
// weight_pulse: [32768, 128, 32] fp32  -> 4096 floats = 1024 float4 per row
// token_ids:    [8, 2048] int32        -> 16384 tokens
// out:          [16384, 4096] fp32
//
// HBM-bound gather-copy at the traffic floor (~459 MB). This revision targets
// DRAM-queue occupancy: 2 tokens per CTA so each warp front-batches 8 LDG.128
// (double the MLP window) and amortizes the dependent token-id load latency
// over 2x the work. Streaming stores (.cs) keep L2 for table-row reuse.

static constexpr int ROW_F4      = 1024;  // 4096 floats / 4
static constexpr int THREADS     = 256;
static constexpr int TOK_PER_CTA = 2;
static constexpr int F4_PER_T    = ROW_F4 / THREADS;  // 4 per token

__device__ __forceinline__ void stcs_f4(float4* addr, const float4& v) {
    asm volatile("st.global.cs.v4.f32 [%0], {%1, %2, %3, %4};"
                 :: "l"(addr), "f"(v.x), "f"(v.y), "f"(v.z), "f"(v.w)
                 : "memory");
}

__global__ void __launch_bounds__(THREADS)
spike_embed_gather2(const int* __restrict__ token_ids,
                    const float4* __restrict__ table,
                    float4* __restrict__ out)
{
    const int tok0 = blockIdx.x * TOK_PER_CTA;
    const int tid  = threadIdx.x;

    // Both token ids up front (independent loads, overlap their latency).
    const int row0 = __ldg(&token_ids[tok0]);
    const int row1 = __ldg(&token_ids[tok0 + 1]);

    const float4* __restrict__ src0 = table + (size_t)row0 * ROW_F4;
    const float4* __restrict__ src1 = table + (size_t)row1 * ROW_F4;
    float4* __restrict__       dst0 = out   + (size_t)tok0 * ROW_F4;
    float4* __restrict__       dst1 = dst0  + ROW_F4;

    // Front-batch all 8 LDG.128 so each warp exposes deep MLP to DRAM.
    float4 v0[F4_PER_T], v1[F4_PER_T];
#pragma unroll
    for (int i = 0; i < F4_PER_T; ++i)
        v0[i] = __ldg(&src0[tid + i * THREADS]);
#pragma unroll
    for (int i = 0; i < F4_PER_T; ++i)
        v1[i] = __ldg(&src1[tid + i * THREADS]);

#pragma unroll
    for (int i = 0; i < F4_PER_T; ++i)
        stcs_f4(&dst0[tid + i * THREADS], v0[i]);
#pragma unroll
    for (int i = 0; i < F4_PER_T; ++i)
        stcs_f4(&dst1[tid + i * THREADS], v1[i]);
}

extern "C" void kernel_launch(void* const* d_in, const int* in_sizes, int n_in,
                              void* d_out, int out_size)
{
    // Resolve input order by element count:
    //   token_ids:    8*2048       = 16384
    //   weight_pulse: 32768*128*32 = 134217728
    const int* token_ids = nullptr;
    const float4* table  = nullptr;
    for (int i = 0; i < n_in; ++i) {
        if (in_sizes[i] == 16384)          token_ids = (const int*)d_in[i];
        else if (in_sizes[i] == 134217728) table     = (const float4*)d_in[i];
    }

    const int n_tokens = 16384;
    spike_embed_gather2<<<n_tokens / TOK_PER_CTA, THREADS>>>(
        token_ids, table, (float4*)d_out);
}